// round 5
// baseline (speedup 1.0000x reference)
#include <cuda_runtime.h>
#include <cstdint>

#define SEQ 16384
#define EMBD 50
#define HID 300
#define G4 1200
#define NTAG 20
#define START_TAG 18
#define STOP_TAG 19
#define NEGV -10000.0f

// ---------------- scratch (static device globals; no allocation) ----------------
__device__ float d_xg[2][SEQ][G4];                     // input projections (bwd stored time-reversed)
__device__ float d_hout[2][SEQ][HID];                  // hf[s], hb[s] (bwd stored un-reversed)
__device__ __align__(16) float d_feats[SEQ][NTAG];
__device__ __align__(16) unsigned char d_bp[SEQ * NTAG];
__device__ int d_best;

// ---------------- kernel 1: embedding + input projection (8 tokens/block) ----------------
#define TPB_E 256
#define TOKB 8
__global__ void k_embed_proj(const int* __restrict__ sent, const float* __restrict__ embed,
                             const float* __restrict__ wf, const float* __restrict__ bfi,
                             const float* __restrict__ bfh,
                             const float* __restrict__ wb, const float* __restrict__ bbi,
                             const float* __restrict__ bbh)
{
    int s0 = blockIdx.x * TOKB;
    __shared__ int toks[TOKB];
    __shared__ float e[TOKB][EMBD];
    int tid = threadIdx.x;
    if (tid < TOKB) toks[tid] = sent[s0 + tid];
    __syncthreads();
    for (int i = tid; i < TOKB * EMBD; i += TPB_E) {
        int u = i / EMBD, k = i - u * EMBD;
        e[u][k] = embed[(size_t)toks[u] * EMBD + k];
    }
    __syncthreads();
    for (int j = tid; j < 2 * G4; j += TPB_E) {
        bool isF = j < G4;
        int jj = isF ? j : j - G4;
        const float* w = (isF ? wf : wb) + (size_t)jj * EMBD;
        float wr[EMBD];
#pragma unroll
        for (int k = 0; k < EMBD; k++) wr[k] = __ldg(&w[k]);
        float b = isF ? (bfi[jj] + bfh[jj]) : (bbi[jj] + bbh[jj]);
#pragma unroll
        for (int u = 0; u < TOKB; u++) {
            float acc = b;
#pragma unroll
            for (int k = 0; k < EMBD; k++) acc = fmaf(e[u][k], wr[k], acc);
            int s = s0 + u;
            if (isF) d_xg[0][s][jj] = acc;
            else     d_xg[1][SEQ - 1 - s][jj] = acc;   // bwd step t consumes emb[SEQ-1-t]
        }
    }
}

// ---------------- kernel 2: cluster LSTM — f32x2 FMA + mbarrier exchange ----------------
__device__ __forceinline__ float sigm(float x) { return 1.0f / (1.0f + expf(-x)); }

#define CELLS_PER 38
#define ROWS_PER 152          // 4 gates * 38 cells
#define KCH 100               // K-chunk per matvec thread (3 chunks = 300)
#define NPAIR 50              // packed f32 pairs per thread
#define MV_THREADS 456        // 3 * 152
#define TPB_L 480
#define HPAD 304
#define PACCP 160

// spin-wait on mbarrier parity, cluster-scope acquire
#define MBAR_WAIT_CLU(addr, parity) \
    asm volatile("{\n\t.reg .pred P;\n\t" \
                 "WL%=:\n\t" \
                 "mbarrier.try_wait.parity.acquire.cluster.shared::cta.b64 P, [%0], %1, 0x989680;\n\t" \
                 "@P bra WD%=;\n\t" \
                 "bra WL%=;\n\t" \
                 "WD%=:\n\t}" :: "r"(addr), "r"(parity) : "memory")

__global__ void __launch_bounds__(TPB_L, 1)
k_lstm(const float* __restrict__ whh_f, const float* __restrict__ whh_b,
       const float* __restrict__ h0, const float* __restrict__ c0in)
{
    __shared__ __align__(16) float h_s[2 * HPAD];      // double-buffered hidden state
    __shared__ float xg_s[ROWS_PER];                   // this step's input projection
    __shared__ float pacc[3 * PACCP];                  // matvec chunk partials
    __shared__ float act[ROWS_PER];                    // activated gates
    __shared__ __align__(8) unsigned long long mbar2[2];  // per-buffer mbarriers (count=8)

    int tid  = threadIdx.x;
    int rank = blockIdx.x & 7;       // cluster rank (contiguous 8-block clusters)
    int dir  = blockIdx.x >> 3;      // cluster 0 = forward, cluster 1 = backward
    int cbase = rank * CELLS_PER;    // rank 7 owns only 34 valid cells (300 = 7*38+34)
    const float* whh = dir ? whh_b : whh_f;
    const float* xg  = &d_xg[dir][0][0];

    // ---- matvec thread mapping: tid = chunk*152 + row ----
    int chunk = tid / ROWS_PER;          // 0..2 for tid < 456
    int row   = tid - chunk * ROWS_PER;  // 0..151
    int mcell = row >> 2, mgate = row & 3;
    int mgc   = cbase + mcell;
    bool mv   = (tid < MV_THREADS) && (mgc < HID);

    // ---- weights into registers as packed f32 pairs ----
    unsigned long long wp[NPAIR];
    {
        const float* wsrc = whh + (mv ? ((size_t)(mgate * HID + mgc) * HID + chunk * KCH) : 0);
#pragma unroll
        for (int i = 0; i < NPAIR; i++) {
            float w0 = mv ? __ldg(&wsrc[2 * i])     : 0.0f;
            float w1 = mv ? __ldg(&wsrc[2 * i + 1]) : 0.0f;
            wp[i] = (unsigned long long)__float_as_uint(w0) |
                    ((unsigned long long)__float_as_uint(w1) << 32);
        }
    }

    // ---- init: hidden state (both buffers), cell state in register, mbarriers ----
    for (int k = tid; k < 2 * HPAD; k += TPB_L) {
        int kk = k % HPAD;
        h_s[k] = (kk < HID) ? h0[dir * HID + kk] : 0.0f;
    }
    float creg = 0.0f;
    if (tid < CELLS_PER && cbase + tid < HID) creg = c0in[dir * HID + cbase + tid];

    unsigned int mb0 = (unsigned int)__cvta_generic_to_shared(&mbar2[0]);
    unsigned int mb1 = (unsigned int)__cvta_generic_to_shared(&mbar2[1]);
    if (tid == 0) {
        asm volatile("mbarrier.init.shared.b64 [%0], %1;" :: "r"(mb0), "r"(8u) : "memory");
        asm volatile("mbarrier.init.shared.b64 [%0], %1;" :: "r"(mb1), "r"(8u) : "memory");
    }

    // ---- xg prefetch setup (one step ahead) ----
    bool xrow = (tid < ROWS_PER) && ((cbase + (tid >> 2)) < HID);
    size_t xoff = xrow ? (size_t)((tid & 3) * HID + cbase + (tid >> 2)) : 0;
    float xnext = xrow ? __ldg(&xg[xoff]) : 0.0f;   // xg[t=0]

    __syncthreads();
    // every CTA's h_s + mbarrier init must complete before any remote traffic
    asm volatile("barrier.cluster.arrive.aligned;" ::: "memory");
    asm volatile("barrier.cluster.wait.aligned;" ::: "memory");

    unsigned int h_smem_base = (unsigned int)__cvta_generic_to_shared(h_s);
    int ph0 = 0, ph1 = 0;

    for (int t = 0; t < SEQ; t++) {
        // wait for all 8 CTAs' h for this step's buffer (buffer 0 at t=0 is pre-init)
        if (t > 0) {
            if (t & 1) { MBAR_WAIT_CLU(mb1, ph1); ph1 ^= 1; }
            else       { MBAR_WAIT_CLU(mb0, ph0); ph0 ^= 1; }
        }

        // publish this step's xg (prefetched last iter); issue next prefetch
        if (tid < ROWS_PER) xg_s[tid] = xnext;
        if (xrow && t + 1 < SEQ) xnext = __ldg(&xg[(size_t)(t + 1) * G4 + xoff]);

        // matvec: packed-pair FMAs, h broadcast from SMEM as 16B loads
        if (tid < MV_THREADS) {
            const ulonglong2* hb = (const ulonglong2*)(h_s + (t & 1) * HPAD + chunk * KCH);
            unsigned long long a0 = 0ull, a1 = 0ull;
#pragma unroll
            for (int i = 0; i < NPAIR / 2; i++) {
                ulonglong2 hp = hb[i];
                asm("fma.rn.f32x2 %0, %1, %2, %0;" : "+l"(a0) : "l"(wp[2 * i]),     "l"(hp.x));
                asm("fma.rn.f32x2 %0, %1, %2, %0;" : "+l"(a1) : "l"(wp[2 * i + 1]), "l"(hp.y));
            }
            float s0 = __uint_as_float((unsigned int)a0) + __uint_as_float((unsigned int)(a0 >> 32));
            float s1 = __uint_as_float((unsigned int)a1) + __uint_as_float((unsigned int)(a1 >> 32));
            pacc[chunk * PACCP + row] = s0 + s1;
        }
        __syncthreads();

        // activation stage: one thread per gate-row (3 sigmoids + 1 tanh in parallel)
        if (tid < ROWS_PER) {
            float g = xg_s[tid] + pacc[tid] + pacc[PACCP + tid] + pacc[2 * PACCP + tid];
            act[tid] = ((tid & 3) == 2) ? tanhf(g) : sigm(g);
        }
        __syncthreads();

        // combine: c/h update + DSMEM broadcast of h into next buffer
        if (tid < CELLS_PER) {
            float iv = act[4 * tid], fv = act[4 * tid + 1];
            float gv = act[4 * tid + 2], ov = act[4 * tid + 3];
            creg = fv * creg + iv * gv;
            float hv = ov * tanhf(creg);
            int gc = cbase + tid;
            if (gc < HID) {
                int pos = dir ? (SEQ - 1 - t) : t;
                d_hout[dir][pos][gc] = hv;
                if (t + 1 < SEQ) {
                    unsigned int dst = h_smem_base + (unsigned int)((((t + 1) & 1) * HPAD + gc) * 4);
#pragma unroll
                    for (int p = 0; p < 8; p++) {
                        unsigned int ra;
                        asm volatile("mapa.shared::cluster.u32 %0, %1, %2;" : "=r"(ra) : "r"(dst), "r"(p));
                        asm volatile("st.shared::cluster.f32 [%0], %1;" :: "r"(ra), "f"(hv));
                    }
                }
            }
        }
        __syncthreads();   // all stores issued before the release fence below

        // elected thread: cluster release fence, then arrive on every peer's next-buffer mbar
        if (t + 1 < SEQ && tid == 0) {
            asm volatile("fence.acq_rel.cluster;" ::: "memory");
            unsigned int mbn = ((t + 1) & 1) ? mb1 : mb0;
#pragma unroll
            for (int p = 0; p < 8; p++) {
                asm volatile("{\n\t.reg .b32 ra;\n\t"
                             "mapa.shared::cluster.u32 ra, %0, %1;\n\t"
                             "mbarrier.arrive.shared::cluster.b64 _, [ra];\n\t}"
                             :: "r"(mbn), "r"(p) : "memory");
            }
        }
    }

    // keep all CTAs alive until every peer is done (no in-flight DSMEM at exit)
    asm volatile("barrier.cluster.arrive.aligned;" ::: "memory");
    asm volatile("barrier.cluster.wait.aligned;" ::: "memory");
}

// ---------------- kernel 3: tag projection (feats) ----------------
__global__ void k_feats(const float* __restrict__ wtag, const float* __restrict__ btag)
{
    int s = blockIdx.x;
    __shared__ float hbuf[2 * HID];
    int tid = threadIdx.x;
    for (int i = tid; i < 2 * HID; i += blockDim.x)
        hbuf[i] = (i < HID) ? d_hout[0][s][i] : d_hout[1][s][i - HID];
    __syncthreads();
    int warp = tid >> 5, lane = tid & 31;
    if (warp < NTAG) {
        const float* w = wtag + warp * 2 * HID;
        float acc = 0;
        for (int k = lane; k < 2 * HID; k += 32)
            acc = fmaf(hbuf[k], __ldg(&w[k]), acc);
#pragma unroll
        for (int off = 16; off; off >>= 1) acc += __shfl_down_sync(0xffffffffu, acc, off);
        if (lane == 0) d_feats[s][warp] = acc + btag[warp];
    }
}

// ---------------- kernel 4: Viterbi forward ----------------
#define VCH 512
#define VIT_SMEM_BYTES (2 * VCH * NTAG * 4)
__global__ void k_viterbi(const float* __restrict__ trans, float* out, int out_size)
{
    extern __shared__ float fb[];   // [2][VCH*NTAG] staged feats
    int tid = threadIdx.x;
    int lane = tid & 31;

    if (tid >= 32) {   // preload chunk 0
        const float4* src = (const float4*)&d_feats[0][0];
        float4* dst = (float4*)fb;
        for (int i = tid - 32; i < VCH * NTAG / 4; i += (int)blockDim.x - 32) dst[i] = src[i];
    }
    __syncthreads();

    float fv = NEGV;
    float trow[NTAG];
    if (tid < 32) {
        if (lane < NTAG) {
            fv = (lane == START_TAG) ? 0.0f : NEGV;
#pragma unroll
            for (int p = 0; p < NTAG; p++) trow[p] = __ldg(&trans[lane * NTAG + p]);
        } else {
#pragma unroll
            for (int p = 0; p < NTAG; p++) trow[p] = 0.0f;
        }
    }

    const int nch = SEQ / VCH;
    for (int c = 0; c < nch; c++) {
        if (tid >= 32) {
            if (c + 1 < nch) {
                const float4* src = (const float4*)&d_feats[(c + 1) * VCH][0];
                float4* dst = (float4*)(fb + ((c + 1) & 1) * VCH * NTAG);
                for (int i = tid - 32; i < VCH * NTAG / 4; i += (int)blockDim.x - 32) dst[i] = src[i];
            }
        } else {
            const float* fbase = fb + (c & 1) * VCH * NTAG;
            for (int j = 0; j < VCH; j++) {
                int t = c * VCH + j;
                float best = -3.4e38f; int bi = 0;
#pragma unroll
                for (int p = 0; p < NTAG; p++) {
                    float v = __shfl_sync(0xffffffffu, fv, p) + trow[p];
                    if (v > best) { best = v; bi = p; }   // strict > == first-max (jnp.argmax)
                }
                if (lane < NTAG) {
                    d_bp[t * NTAG + lane] = (unsigned char)bi;
                    fv = best + fbase[j * NTAG + lane];
                }
            }
        }
        __syncthreads();
    }

    if (tid < 32) {
        float term = (lane < NTAG) ? (fv + __ldg(&trans[STOP_TAG * NTAG + lane])) : -3.4e38f;
        float best = -3.4e38f; int bi = 0;
#pragma unroll
        for (int p = 0; p < NTAG; p++) {
            float v = __shfl_sync(0xffffffffu, term, p);
            if (v > best) { best = v; bi = p; }
        }
        if (lane == 0) {
            d_best = bi;
            if (out_size > SEQ) out[0] = best;   // score at out[0] when layout has room
        }
    }
}

// ---------------- kernel 5: backtrace ----------------
#define BCH 1024
__global__ void k_backtrace(float* out, int out_size)
{
    __shared__ unsigned char bb[2][BCH * NTAG];
    int tid = threadIdx.x;
    const int nch = SEQ / BCH;
    if (tid >= 32) {   // preload last chunk
        const uint4* src = (const uint4*)&d_bp[(size_t)(nch - 1) * BCH * NTAG];
        uint4* dst = (uint4*)bb[(nch - 1) & 1];
        for (int i = tid - 32; i < BCH * NTAG / 16; i += (int)blockDim.x - 32) dst[i] = src[i];
    }
    __syncthreads();
    int off = (out_size > SEQ) ? (out_size - SEQ) : 0;
    int tag = d_best;
    for (int c = nch - 1; c >= 0; c--) {
        if (tid >= 32) {
            if (c > 0) {
                const uint4* src = (const uint4*)&d_bp[(size_t)(c - 1) * BCH * NTAG];
                uint4* dst = (uint4*)bb[(c - 1) & 1];
                for (int i = tid - 32; i < BCH * NTAG / 16; i += (int)blockDim.x - 32) dst[i] = src[i];
            }
        } else if (tid == 0) {
            const unsigned char* b = bb[c & 1];
            for (int j = BCH - 1; j >= 0; j--) {
                int s = c * BCH + j;
                out[off + s] = (float)tag;     // y[s] = tag entering step s's backpointer
                tag = b[j * NTAG + tag];       // carry = bp[s][tag]
            }
        }
        __syncthreads();
    }
}

// ---------------- launch ----------------
extern "C" void kernel_launch(void* const* d_in, const int* in_sizes, int n_in,
                              void* d_out, int out_size)
{
    const int*   sent  = (const int*)d_in[0];
    const float* embed = (const float*)d_in[1];
    const float* wihf  = (const float*)d_in[2];
    const float* whhf  = (const float*)d_in[3];
    const float* bihf  = (const float*)d_in[4];
    const float* bhhf  = (const float*)d_in[5];
    const float* wihb  = (const float*)d_in[6];
    const float* whhb  = (const float*)d_in[7];
    const float* bihb  = (const float*)d_in[8];
    const float* bhhb  = (const float*)d_in[9];
    const float* h0    = (const float*)d_in[10];
    const float* c0    = (const float*)d_in[11];
    const float* wtag  = (const float*)d_in[12];
    const float* btag  = (const float*)d_in[13];
    const float* trans = (const float*)d_in[14];
    float* out = (float*)d_out;

    cudaFuncSetAttribute(k_viterbi, cudaFuncAttributeMaxDynamicSharedMemorySize, VIT_SMEM_BYTES);

    // 1) embedding + input projections (8 tokens per block)
    k_embed_proj<<<SEQ / TOKB, TPB_E>>>(sent, embed, wihf, bihf, bhhf, wihb, bihb, bhhb);

    // 2) BiLSTM recurrence: 16 CTAs = 2 clusters of 8 (fwd / bwd)
    {
        cudaLaunchConfig_t cfg = {};
        cfg.gridDim = dim3(16, 1, 1);
        cfg.blockDim = dim3(TPB_L, 1, 1);
        cfg.dynamicSmemBytes = 0;
        cfg.stream = 0;
        cudaLaunchAttribute attrs[1];
        attrs[0].id = cudaLaunchAttributeClusterDimension;
        attrs[0].val.clusterDim.x = 8;
        attrs[0].val.clusterDim.y = 1;
        attrs[0].val.clusterDim.z = 1;
        cfg.attrs = attrs;
        cfg.numAttrs = 1;
        cudaLaunchKernelEx(&cfg, k_lstm, whhf, whhb, h0, c0);
    }

    // 3) tag projection
    k_feats<<<SEQ, 640>>>(wtag, btag);

    // 4) Viterbi forward (single block: 1 compute warp + 7 loader warps)
    k_viterbi<<<1, 256, VIT_SMEM_BYTES>>>(trans, out, out_size);

    // 5) backtrace
    k_backtrace<<<1, 256>>>(out, out_size);
}

// round 6
// speedup vs baseline: 1.0908x; 1.0908x over previous
#include <cuda_runtime.h>
#include <cstdint>

#define SEQ 16384
#define EMBD 50
#define HID 300
#define G4 1200
#define NTAG 20
#define START_TAG 18
#define STOP_TAG 19
#define NEGV -10000.0f

// ---------------- scratch (static device globals; no allocation) ----------------
__device__ float d_xg[2][SEQ][G4];                     // input projections (bwd stored time-reversed)
__device__ float d_hout[2][SEQ][HID];                  // hf[s], hb[s] (bwd stored un-reversed)
__device__ __align__(16) float d_feats[SEQ][NTAG];
__device__ __align__(16) unsigned char d_bp[SEQ * NTAG];
__device__ int d_best;

// ---------------- kernel 1: embedding + input projection (8 tokens/block) ----------------
#define TPB_E 256
#define TOKB 8
__global__ void k_embed_proj(const int* __restrict__ sent, const float* __restrict__ embed,
                             const float* __restrict__ wf, const float* __restrict__ bfi,
                             const float* __restrict__ bfh,
                             const float* __restrict__ wb, const float* __restrict__ bbi,
                             const float* __restrict__ bbh)
{
    int s0 = blockIdx.x * TOKB;
    __shared__ int toks[TOKB];
    __shared__ float e[TOKB][EMBD];
    int tid = threadIdx.x;
    if (tid < TOKB) toks[tid] = sent[s0 + tid];
    __syncthreads();
    for (int i = tid; i < TOKB * EMBD; i += TPB_E) {
        int u = i / EMBD, k = i - u * EMBD;
        e[u][k] = embed[(size_t)toks[u] * EMBD + k];
    }
    __syncthreads();
    for (int j = tid; j < 2 * G4; j += TPB_E) {
        bool isF = j < G4;
        int jj = isF ? j : j - G4;
        const float* w = (isF ? wf : wb) + (size_t)jj * EMBD;
        float wr[EMBD];
#pragma unroll
        for (int k = 0; k < EMBD; k++) wr[k] = __ldg(&w[k]);
        float b = isF ? (bfi[jj] + bfh[jj]) : (bbi[jj] + bbh[jj]);
#pragma unroll
        for (int u = 0; u < TOKB; u++) {
            float acc = b;
#pragma unroll
            for (int k = 0; k < EMBD; k++) acc = fmaf(e[u][k], wr[k], acc);
            int s = s0 + u;
            if (isF) d_xg[0][s][jj] = acc;
            else     d_xg[1][SEQ - 1 - s][jj] = acc;   // bwd step t consumes emb[SEQ-1-t]
        }
    }
}

// ---------------- kernel 2: cluster LSTM — f32x2 FMA + shuffle-fused epilogue ----------------
__device__ __forceinline__ float sigm(float x) { return 1.0f / (1.0f + expf(-x)); }

#define CELLS_PER 38
#define ROWS_PER 152          // 4 gates * 38 cells
#define RPAD 160              // rows padded to 5 full warps for shuffle epilogue
#define KCH 100               // K-chunk per matvec thread (3 chunks = 300)
#define NPAIR 50              // packed f32 pairs per thread
#define MV_THREADS 456        // 3 * 152
#define TPB_L 480
#define HPAD 304
#define PACCP 160

__global__ void __launch_bounds__(TPB_L, 1)
k_lstm(const float* __restrict__ whh_f, const float* __restrict__ whh_b,
       const float* __restrict__ h0, const float* __restrict__ c0in)
{
    __shared__ __align__(16) float h_s[2 * HPAD];      // double-buffered hidden state
    __shared__ float xg_s[RPAD];                       // this step's input projection
    __shared__ float pacc[3 * PACCP];                  // matvec chunk partials

    int tid  = threadIdx.x;
    int rank = blockIdx.x & 7;       // cluster rank (contiguous 8-block clusters)
    int dir  = blockIdx.x >> 3;      // cluster 0 = forward, cluster 1 = backward
    int cbase = rank * CELLS_PER;    // rank 7 owns only 34 valid cells (300 = 7*38+34)
    const float* whh = dir ? whh_b : whh_f;
    const float* xg  = &d_xg[dir][0][0];

    // ---- matvec thread mapping: tid = chunk*152 + row (chunk-0 threads == rows 0..151) ----
    int chunk = tid / ROWS_PER;          // 0..2 for tid < 456
    int row   = tid - chunk * ROWS_PER;  // 0..151
    int mcell = row >> 2, mgate = row & 3;
    int mgc   = cbase + mcell;
    bool mv   = (tid < MV_THREADS) && (mgc < HID);

    // ---- weights into registers as packed f32 pairs ----
    unsigned long long wp[NPAIR];
    {
        const float* wsrc = whh + (mv ? ((size_t)(mgate * HID + mgc) * HID + chunk * KCH) : 0);
#pragma unroll
        for (int i = 0; i < NPAIR; i++) {
            float w0 = mv ? __ldg(&wsrc[2 * i])     : 0.0f;
            float w1 = mv ? __ldg(&wsrc[2 * i + 1]) : 0.0f;
            wp[i] = (unsigned long long)__float_as_uint(w0) |
                    ((unsigned long long)__float_as_uint(w1) << 32);
        }
    }

    // ---- init hidden state (both buffers), pad rows, cell state in register ----
    for (int k = tid; k < 2 * HPAD; k += TPB_L) {
        int kk = k % HPAD;
        h_s[k] = (kk < HID) ? h0[dir * HID + kk] : 0.0f;
    }
    if (tid < RPAD) { xg_s[tid] = 0.0f; }
    for (int k = tid; k < 3 * PACCP; k += TPB_L) pacc[k] = 0.0f;  // pad rows stay 0 forever

    // cell state lives on gate-0 epilogue threads: tid = 4*cell
    float creg = 0.0f;
    if ((tid & 3) == 0 && (tid >> 2) < CELLS_PER && cbase + (tid >> 2) < HID)
        creg = c0in[dir * HID + cbase + (tid >> 2)];

    // ---- xg prefetch setup (one step ahead) ----
    bool xrow = (tid < ROWS_PER) && ((cbase + (tid >> 2)) < HID);
    size_t xoff = xrow ? (size_t)((tid & 3) * HID + cbase + (tid >> 2)) : 0;
    float xnext = xrow ? __ldg(&xg[xoff]) : 0.0f;   // xg[t=0]

    __syncthreads();
    // all CTAs finish h_s init before anyone's step-0 remote stores land
    asm volatile("barrier.cluster.arrive.aligned;" ::: "memory");
    asm volatile("barrier.cluster.wait.aligned;" ::: "memory");

    unsigned int h_smem_base = (unsigned int)__cvta_generic_to_shared(h_s);

    for (int t = 0; t < SEQ; t++) {
        // publish this step's xg (prefetched last iter); issue next prefetch
        if (tid < ROWS_PER) xg_s[tid] = xnext;
        if (xrow && t + 1 < SEQ) xnext = __ldg(&xg[(size_t)(t + 1) * G4 + xoff]);

        // matvec: packed-pair FMAs, h broadcast from SMEM via 16B loads
        if (tid < MV_THREADS) {
            const ulonglong2* hb = (const ulonglong2*)(h_s + (t & 1) * HPAD + chunk * KCH);
            unsigned long long a0 = 0ull, a1 = 0ull;
#pragma unroll
            for (int i = 0; i < NPAIR / 2; i++) {
                ulonglong2 hp = hb[i];
                asm("fma.rn.f32x2 %0, %1, %2, %0;" : "+l"(a0) : "l"(wp[2 * i]),     "l"(hp.x));
                asm("fma.rn.f32x2 %0, %1, %2, %0;" : "+l"(a1) : "l"(wp[2 * i + 1]), "l"(hp.y));
            }
            float s0 = __uint_as_float((unsigned int)a0) + __uint_as_float((unsigned int)(a0 >> 32));
            float s1 = __uint_as_float((unsigned int)a1) + __uint_as_float((unsigned int)(a1 >> 32));
            pacc[chunk * PACCP + row] = s0 + s1;
        }
        __syncthreads();

        // fused epilogue: 5 full warps reduce + activate, shuffle-exchange, gate-0 combines
        if (tid < RPAD) {
            float g = xg_s[tid] + pacc[tid] + pacc[PACCP + tid] + pacc[2 * PACCP + tid];
            float a = ((tid & 3) == 2) ? tanhf(g) : sigm(g);
            int lb = (tid & 31) & ~3;
            float ai = __shfl_sync(0xffffffffu, a, lb + 0);
            float af = __shfl_sync(0xffffffffu, a, lb + 1);
            float ag = __shfl_sync(0xffffffffu, a, lb + 2);
            float ao = __shfl_sync(0xffffffffu, a, lb + 3);
            if ((tid & 3) == 0) {
                int cell = tid >> 2;
                if (cell < CELLS_PER) {
                    creg = af * creg + ai * ag;
                    float hv = ao * tanhf(creg);
                    int gc = cbase + cell;
                    if (gc < HID) {
                        int pos = dir ? (SEQ - 1 - t) : t;
                        d_hout[dir][pos][gc] = hv;
                        if (t + 1 < SEQ) {
                            unsigned int dst = h_smem_base +
                                (unsigned int)((((t + 1) & 1) * HPAD + gc) * 4);
#pragma unroll
                            for (int p = 0; p < 8; p++) {
                                unsigned int ra;
                                asm volatile("mapa.shared::cluster.u32 %0, %1, %2;"
                                             : "=r"(ra) : "r"(dst), "r"(p));
                                asm volatile("st.shared::cluster.f32 [%0], %1;"
                                             :: "r"(ra), "f"(hv));
                            }
                        }
                    }
                }
            }
        }
        // release our h writes / acquire peers' writes (also orders xg_s/pacc reuse)
        asm volatile("barrier.cluster.arrive.aligned;" ::: "memory");
        asm volatile("barrier.cluster.wait.aligned;" ::: "memory");
    }
}

// ---------------- kernel 3: tag projection (feats) ----------------
__global__ void k_feats(const float* __restrict__ wtag, const float* __restrict__ btag)
{
    int s = blockIdx.x;
    __shared__ float hbuf[2 * HID];
    int tid = threadIdx.x;
    for (int i = tid; i < 2 * HID; i += blockDim.x)
        hbuf[i] = (i < HID) ? d_hout[0][s][i] : d_hout[1][s][i - HID];
    __syncthreads();
    int warp = tid >> 5, lane = tid & 31;
    if (warp < NTAG) {
        const float* w = wtag + warp * 2 * HID;
        float acc = 0;
        for (int k = lane; k < 2 * HID; k += 32)
            acc = fmaf(hbuf[k], __ldg(&w[k]), acc);
#pragma unroll
        for (int off = 16; off; off >>= 1) acc += __shfl_down_sync(0xffffffffu, acc, off);
        if (lane == 0) d_feats[s][warp] = acc + btag[warp];
    }
}

// ---------------- kernel 4: Viterbi forward ----------------
#define VCH 512
#define VIT_SMEM_BYTES (2 * VCH * NTAG * 4)
__global__ void k_viterbi(const float* __restrict__ trans, float* out, int out_size)
{
    extern __shared__ float fb[];   // [2][VCH*NTAG] staged feats
    int tid = threadIdx.x;
    int lane = tid & 31;

    if (tid >= 32) {   // preload chunk 0
        const float4* src = (const float4*)&d_feats[0][0];
        float4* dst = (float4*)fb;
        for (int i = tid - 32; i < VCH * NTAG / 4; i += (int)blockDim.x - 32) dst[i] = src[i];
    }
    __syncthreads();

    float fv = NEGV;
    float trow[NTAG];
    if (tid < 32) {
        if (lane < NTAG) {
            fv = (lane == START_TAG) ? 0.0f : NEGV;
#pragma unroll
            for (int p = 0; p < NTAG; p++) trow[p] = __ldg(&trans[lane * NTAG + p]);
        } else {
#pragma unroll
            for (int p = 0; p < NTAG; p++) trow[p] = 0.0f;
        }
    }

    const int nch = SEQ / VCH;
    for (int c = 0; c < nch; c++) {
        if (tid >= 32) {
            if (c + 1 < nch) {
                const float4* src = (const float4*)&d_feats[(c + 1) * VCH][0];
                float4* dst = (float4*)(fb + ((c + 1) & 1) * VCH * NTAG);
                for (int i = tid - 32; i < VCH * NTAG / 4; i += (int)blockDim.x - 32) dst[i] = src[i];
            }
        } else {
            const float* fbase = fb + (c & 1) * VCH * NTAG;
            for (int j = 0; j < VCH; j++) {
                int t = c * VCH + j;
                float best = -3.4e38f; int bi = 0;
#pragma unroll
                for (int p = 0; p < NTAG; p++) {
                    float v = __shfl_sync(0xffffffffu, fv, p) + trow[p];
                    if (v > best) { best = v; bi = p; }   // strict > == first-max (jnp.argmax)
                }
                if (lane < NTAG) {
                    d_bp[t * NTAG + lane] = (unsigned char)bi;
                    fv = best + fbase[j * NTAG + lane];
                }
            }
        }
        __syncthreads();
    }

    if (tid < 32) {
        float term = (lane < NTAG) ? (fv + __ldg(&trans[STOP_TAG * NTAG + lane])) : -3.4e38f;
        float best = -3.4e38f; int bi = 0;
#pragma unroll
        for (int p = 0; p < NTAG; p++) {
            float v = __shfl_sync(0xffffffffu, term, p);
            if (v > best) { best = v; bi = p; }
        }
        if (lane == 0) {
            d_best = bi;
            if (out_size > SEQ) out[0] = best;   // score at out[0] when layout has room
        }
    }
}

// ---------------- kernel 5: backtrace ----------------
#define BCH 1024
__global__ void k_backtrace(float* out, int out_size)
{
    __shared__ unsigned char bb[2][BCH * NTAG];
    int tid = threadIdx.x;
    const int nch = SEQ / BCH;
    if (tid >= 32) {   // preload last chunk
        const uint4* src = (const uint4*)&d_bp[(size_t)(nch - 1) * BCH * NTAG];
        uint4* dst = (uint4*)bb[(nch - 1) & 1];
        for (int i = tid - 32; i < BCH * NTAG / 16; i += (int)blockDim.x - 32) dst[i] = src[i];
    }
    __syncthreads();
    int off = (out_size > SEQ) ? (out_size - SEQ) : 0;
    int tag = d_best;
    for (int c = nch - 1; c >= 0; c--) {
        if (tid >= 32) {
            if (c > 0) {
                const uint4* src = (const uint4*)&d_bp[(size_t)(c - 1) * BCH * NTAG];
                uint4* dst = (uint4*)bb[(c - 1) & 1];
                for (int i = tid - 32; i < BCH * NTAG / 16; i += (int)blockDim.x - 32) dst[i] = src[i];
            }
        } else if (tid == 0) {
            const unsigned char* b = bb[c & 1];
            for (int j = BCH - 1; j >= 0; j--) {
                int s = c * BCH + j;
                out[off + s] = (float)tag;     // y[s] = tag entering step s's backpointer
                tag = b[j * NTAG + tag];       // carry = bp[s][tag]
            }
        }
        __syncthreads();
    }
}

// ---------------- launch ----------------
extern "C" void kernel_launch(void* const* d_in, const int* in_sizes, int n_in,
                              void* d_out, int out_size)
{
    const int*   sent  = (const int*)d_in[0];
    const float* embed = (const float*)d_in[1];
    const float* wihf  = (const float*)d_in[2];
    const float* whhf  = (const float*)d_in[3];
    const float* bihf  = (const float*)d_in[4];
    const float* bhhf  = (const float*)d_in[5];
    const float* wihb  = (const float*)d_in[6];
    const float* whhb  = (const float*)d_in[7];
    const float* bihb  = (const float*)d_in[8];
    const float* bhhb  = (const float*)d_in[9];
    const float* h0    = (const float*)d_in[10];
    const float* c0    = (const float*)d_in[11];
    const float* wtag  = (const float*)d_in[12];
    const float* btag  = (const float*)d_in[13];
    const float* trans = (const float*)d_in[14];
    float* out = (float*)d_out;

    cudaFuncSetAttribute(k_viterbi, cudaFuncAttributeMaxDynamicSharedMemorySize, VIT_SMEM_BYTES);

    // 1) embedding + input projections (8 tokens per block)
    k_embed_proj<<<SEQ / TOKB, TPB_E>>>(sent, embed, wihf, bihf, bhhf, wihb, bihb, bhhb);

    // 2) BiLSTM recurrence: 16 CTAs = 2 clusters of 8 (fwd / bwd)
    {
        cudaLaunchConfig_t cfg = {};
        cfg.gridDim = dim3(16, 1, 1);
        cfg.blockDim = dim3(TPB_L, 1, 1);
        cfg.dynamicSmemBytes = 0;
        cfg.stream = 0;
        cudaLaunchAttribute attrs[1];
        attrs[0].id = cudaLaunchAttributeClusterDimension;
        attrs[0].val.clusterDim.x = 8;
        attrs[0].val.clusterDim.y = 1;
        attrs[0].val.clusterDim.z = 1;
        cfg.attrs = attrs;
        cfg.numAttrs = 1;
        cudaLaunchKernelEx(&cfg, k_lstm, whhf, whhb, h0, c0);
    }

    // 3) tag projection
    k_feats<<<SEQ, 640>>>(wtag, btag);

    // 4) Viterbi forward (single block: 1 compute warp + 7 loader warps)
    k_viterbi<<<1, 256, VIT_SMEM_BYTES>>>(trans, out, out_size);

    // 5) backtrace
    k_backtrace<<<1, 256>>>(out, out_size);
}